// round 14
// baseline (speedup 1.0000x reference)
#include <cuda_runtime.h>
#include <cuda_bf16.h>
#include <cuda_fp16.h>
#include <cstdint>

#define NBATCH 65536

// ---------------- static scratch (no runtime allocation) ----------------
__device__ __align__(16) __half g_h1[(size_t)NBATCH * 320];
__device__ __align__(16) __half g_h2[(size_t)NBATCH * 128];
__device__ float g_sum1[320], g_sq1[320], g_scale1[320], g_shift1[320];
__device__ float g_sum2[128], g_sq2[128], g_scale2[128], g_shift2[128];
__device__ __align__(16) __half gW1h[320 * 832];
__device__ __align__(16) __half gW2h[128 * 320];

// ---------------- helpers ----------------
__device__ __forceinline__ uint32_t smem_u32(const void* p) {
    uint32_t a;
    asm("{ .reg .u64 t; cvta.to.shared.u64 t, %1; cvt.u32.u64 %0, t; }" : "=r"(a) : "l"(p));
    return a;
}
__device__ __forceinline__ void cpa16(uint32_t dst, const void* src) {
    asm volatile("cp.async.cg.shared.global [%0], [%1], 16;" :: "r"(dst), "l"(src));
}
#define CP_COMMIT() asm volatile("cp.async.commit_group;" ::: "memory")
#define CP_WAIT0()  asm volatile("cp.async.wait_group 0;" ::: "memory")

__device__ __forceinline__ void mma16h(float* c, const uint32_t* a, const uint32_t* b) {
    asm volatile(
        "mma.sync.aligned.m16n8k16.row.col.f32.f16.f16.f32 "
        "{%0,%1,%2,%3},{%4,%5,%6,%7},{%8,%9},{%0,%1,%2,%3};\n"
        : "+f"(c[0]), "+f"(c[1]), "+f"(c[2]), "+f"(c[3])
        : "r"(a[0]), "r"(a[1]), "r"(a[2]), "r"(a[3]), "r"(b[0]), "r"(b[1]));
}
__device__ __forceinline__ void mma16(float* c, const uint32_t* a, const uint32_t* b) {
    asm volatile(
        "mma.sync.aligned.m16n8k16.row.col.f32.bf16.bf16.f32 "
        "{%0,%1,%2,%3},{%4,%5,%6,%7},{%8,%9},{%0,%1,%2,%3};\n"
        : "+f"(c[0]), "+f"(c[1]), "+f"(c[2]), "+f"(c[3])
        : "r"(a[0]), "r"(a[1]), "r"(a[2]), "r"(a[3]), "r"(b[0]), "r"(b[1]));
}

__device__ __forceinline__ void ldsm4(uint32_t a, uint32_t& r0, uint32_t& r1,
                                      uint32_t& r2, uint32_t& r3) {
    asm volatile("ldmatrix.sync.aligned.m8n8.x4.shared.b16 {%0,%1,%2,%3}, [%4];"
                 : "=r"(r0), "=r"(r1), "=r"(r2), "=r"(r3) : "r"(a));
}

// fp16 convert (single term)
__device__ __forceinline__ void conv4h(float4 v, uint2& hi) {
    __half2 H0 = __halves2half2(__float2half_rn(v.x), __float2half_rn(v.y));
    __half2 H1 = __halves2half2(__float2half_rn(v.z), __float2half_rn(v.w));
    hi.x = *reinterpret_cast<uint32_t*>(&H0);
    hi.y = *reinterpret_cast<uint32_t*>(&H1);
}
__device__ __forceinline__ float4 h4_to_f4(uint2 u) {
    __half2 a = *reinterpret_cast<__half2*>(&u.x);
    __half2 b = *reinterpret_cast<__half2*>(&u.y);
    float2 fa = __half22float2(a), fb = __half22float2(b);
    return make_float4(fa.x, fa.y, fb.x, fb.y);
}
// bf16 split (layer 3)
__device__ __forceinline__ void split4v(float4 v, uint2& hi, uint2& lo) {
    __nv_bfloat16 ax = __float2bfloat16(v.x), ay = __float2bfloat16(v.y);
    __nv_bfloat16 az = __float2bfloat16(v.z), aw = __float2bfloat16(v.w);
    float rx = v.x - __bfloat162float(ax), ry = v.y - __bfloat162float(ay);
    float rz = v.z - __bfloat162float(az), rw = v.w - __bfloat162float(aw);
    __nv_bfloat162 H0 = __halves2bfloat162(ax, ay), H1 = __halves2bfloat162(az, aw);
    __nv_bfloat162 L0 = __halves2bfloat162(__float2bfloat16(rx), __float2bfloat16(ry));
    __nv_bfloat162 L1 = __halves2bfloat162(__float2bfloat16(rz), __float2bfloat16(rw));
    hi.x = *reinterpret_cast<uint32_t*>(&H0); hi.y = *reinterpret_cast<uint32_t*>(&H1);
    lo.x = *reinterpret_cast<uint32_t*>(&L0); lo.y = *reinterpret_cast<uint32_t*>(&L1);
}

// ---------------- weight pre-convert (fp16, zero padded) ----------------
__global__ void split_w1(const float* __restrict__ W1) {
    int idx = blockIdx.x * 256 + threadIdx.x;
    if (idx >= 320 * 832) return;
    int n = idx / 832, k = idx % 832;
    float v = (n < 300 && k < 784) ? W1[n * 784 + k] : 0.f;
    gW1h[idx] = __float2half_rn(v);
}
__global__ void split_w2(const float* __restrict__ W2) {
    int idx = blockIdx.x * 256 + threadIdx.x;
    if (idx >= 128 * 320) return;
    int n = idx / 320, k = idx % 320;
    float v = (n < 100 && k < 300) ? W2[n * 300 + k] : 0.f;
    gW2h[idx] = __float2half_rn(v);
}

// ---------------- fused GEMM (1-term fp16, K-chunk 32) -------------------------------
// MODE 1: h1 = relu(x @ W1^T + b1), fused stats  [K=784, CTA 64x160, 128 thr, 4 CTA/SM]
// MODE 2: h2 = relu((s1*(sc1*h1+sh1)+m1) @ W2^T + b2), fused stats
//                                                [K=300, CTA 64x128, 256 thr, 2 CTA/SM]
template <int MODE>
__global__ void __launch_bounds__(MODE == 1 ? 128 : 256, MODE == 1 ? 4 : 2)
tc_gemm(const float* __restrict__ X, const float* __restrict__ bias,
        const float* __restrict__ S, const float* __restrict__ Mn)
{
    constexpr int THR  = (MODE == 1) ? 128 : 256;
    constexpr int NT   = (MODE == 1) ? 160 : 128;   // CTA N tile
    constexpr int WNW  = (MODE == 1) ? 2 : 4;       // warps along N
    constexpr int WN   = NT / WNW;                  // warp N tile (80 / 32)
    constexpr int J    = WN / 8;                    // n-frags per warp (10 / 4)
    constexpr int JP   = J / 2;                     // ldsm4 pairs (5 / 2)
    constexpr int KV   = (MODE == 1) ? 784 : 300;
    constexpr int KSTG = (MODE == 1) ? 25 : 10;     // K chunks of 32 (W zero-padded)
    constexpr int OSTR = (MODE == 1) ? 320 : 128;
    constexpr int WSTR = (MODE == 1) ? 832 : 320;
    constexpr int NVG  = (MODE == 1) ? 300 : 100;
    constexpr int PIT  = 20;                        // words per row (80 B)
    constexpr int ABUF = 64 * PIT * 4;              // 5120 B per buf
    constexpr int BBUF = NT * PIT * 4;              // 12800 / 10240 per buf
    constexpr int OFF_B  = 2 * ABUF;
    constexpr int OFF_SC = OFF_B + 2 * BBUF;
    constexpr int CH = NT * 4;                      // 16B chunks per stage

    extern __shared__ __align__(16) char smc[];
    const uint32_t sb = smem_u32(smc);

    const int tid  = threadIdx.x;
    const int lane = tid & 31;
    const int wid  = tid >> 5;
    const int wm   = (MODE == 1) ? (wid >> 1) : (wid >> 2);   // 0..1
    const int wn   = (MODE == 1) ? (wid & 1)  : (wid & 3);    // 0..WNW-1
    const int mblk = blockIdx.x * 64;
    const int nbase = (MODE == 1) ? blockIdx.y * 160 : 0;

    const __half* Wh = (MODE == 1) ? gW1h : gW2h;
    __half* OUT = (MODE == 1) ? g_h1 : g_h2;
    float* sumP = (MODE == 1) ? g_sum1 : g_sum2;
    float* sqP  = (MODE == 1) ? g_sq1  : g_sq2;

    float* sScale = (float*)(smc + OFF_SC);
    float* sShift = (float*)(smc + OFF_SC + 1280);
    if (MODE == 2) {
        for (int i = tid; i < KV; i += THR) {
            sScale[i] = g_scale1[i];
            sShift[i] = g_shift1[i];
        }
        __syncthreads();
    }

    float acc[2][J][4];
#pragma unroll
    for (int i = 0; i < 2; i++)
#pragma unroll
        for (int j = 0; j < J; j++)
#pragma unroll
            for (int c = 0; c < 4; c++) acc[i][j][c] = 0.f;

    // A producer geometry
    const int arow = (MODE == 1) ? (tid >> 1) : (tid >> 2);   // 0..63
    const int asub = (MODE == 1) ? (tid & 1)  : (tid & 3);

    float4 va[(MODE == 1) ? 4 : 2];

    auto LDA = [&](int c) {
        const size_t m = (size_t)(mblk + arow);
        if (MODE == 1) {
            const int k0 = c * 32 + asub * 16;
#pragma unroll
            for (int q = 0; q < 4; ++q) {
                const int kk = k0 + q * 4;
                va[q] = (kk + 3 < KV) ? *(const float4*)(X + m * 784 + kk)
                                      : make_float4(0.f, 0.f, 0.f, 0.f);
            }
        } else {
            const int k0 = c * 32 + asub * 4;
#pragma unroll
            for (int q = 0; q < 2; ++q) {
                const int kk = k0 + q * 16;
                float4 o;
                if (kk + 3 < KV) {
                    float4 h  = h4_to_f4(*(const uint2*)(g_h1 + m * 320 + kk));
                    float4 s  = *(const float4*)(S + m * 300 + kk);
                    float4 q2 = *(const float4*)(Mn + m * 300 + kk);
                    float4 sc = *(const float4*)(sScale + kk);
                    float4 sh = *(const float4*)(sShift + kk);
                    o.x = fmaf(s.x, fmaf(sc.x, h.x, sh.x), q2.x);
                    o.y = fmaf(s.y, fmaf(sc.y, h.y, sh.y), q2.y);
                    o.z = fmaf(s.z, fmaf(sc.z, h.z, sh.z), q2.z);
                    o.w = fmaf(s.w, fmaf(sc.w, h.w, sh.w), q2.w);
                } else o = make_float4(0.f, 0.f, 0.f, 0.f);
                va[q] = o;
            }
        }
    };

    auto STSA = [&](int buf) {
        uint32_t* pH = (uint32_t*)(smc + buf * ABUF);
        if (MODE == 1) {
#pragma unroll
            for (int q = 0; q < 4; ++q) {
                uint2 hi;
                conv4h(va[q], hi);
                const int b0 = arow * PIT + asub * 8 + q * 2;
                *(uint2*)(pH + b0) = hi;
            }
        } else {
#pragma unroll
            for (int q = 0; q < 2; ++q) {
                uint2 hi;
                conv4h(va[q], hi);
                const int b0 = arow * PIT + asub * 2 + q * 8;
                *(uint2*)(pH + b0) = hi;
            }
        }
    };

    auto CPB = [&](int c, int buf) {
        constexpr int ITER = CH / THR;   // 5 (MODE1) or 2 (MODE2)
#pragma unroll
        for (int i = 0; i < ITER; ++i) {
            const int it = tid + i * THR;
            const int r  = it >> 2, c4 = it & 3;
            const __half* src = Wh + (size_t)(nbase + r) * WSTR + c * 32 + c4 * 8;
            const uint32_t dst = sb + OFF_B + buf * BBUF + (r * PIT + c4 * 4) * 4;
            cpa16(dst, src);
        }
        CP_COMMIT();
    };

    // ldmatrix lane addresses (pitch 20 words = 80 B, conflict-free)
    const uint32_t aBase = sb + ((uint32_t)(wm * 32 + (lane & 15)) * PIT + ((lane >> 4) << 2)) * 4;
    const uint32_t bBase = sb + OFF_B +
        ((uint32_t)(wn * WN + ((lane >> 4) << 3) + (lane & 7)) * PIT + (((lane >> 3) & 1) << 2)) * 4;
    constexpr uint32_t AROW16 = 16 * PIT * 4;    // 1280
    constexpr uint32_t BROW16 = 16 * PIT * 4;    // 1280 per j-pair

    // prologue
    LDA(0);
    CPB(0, 0);
    STSA(0);
    CP_WAIT0();
    __syncthreads();

    const int fr = lane >> 2;   // 0..7
    const int fq = lane & 3;    // 0..3

    for (int c = 0; c < KSTG; ++c) {
        const int cur = c & 1;
        if (c + 1 < KSTG) { LDA(c + 1); CPB(c + 1, cur ^ 1); }

        const uint32_t aOff = (uint32_t)cur * ABUF;
        const uint32_t bOff = (uint32_t)cur * BBUF;

#pragma unroll
        for (int kk = 0; kk < 2; ++kk) {
            const uint32_t kb = kk * 32;   // 16 fp16 = 32 bytes per kk
            uint32_t ah0[4], ah1[4];
            ldsm4(aBase + aOff + kb,          ah0[0], ah0[1], ah0[2], ah0[3]);
            ldsm4(aBase + aOff + AROW16 + kb, ah1[0], ah1[1], ah1[2], ah1[3]);
#pragma unroll
            for (int jp = 0; jp < JP; ++jp) {
                uint32_t b4[4];   // two n-frags, JIT load (4 live regs)
                ldsm4(bBase + bOff + (uint32_t)jp * BROW16 + kb,
                      b4[0], b4[1], b4[2], b4[3]);
                mma16h(acc[0][2 * jp],     ah0, b4);
                mma16h(acc[1][2 * jp],     ah1, b4);
                mma16h(acc[0][2 * jp + 1], ah0, b4 + 2);
                mma16h(acc[1][2 * jp + 1], ah1, b4 + 2);
            }
        }

        if (c + 1 < KSTG) { STSA(cur ^ 1); CP_WAIT0(); }
        __syncthreads();
    }

    // ---- epilogue: bias + relu + fp16 store + fused column stats ----
    const int r0 = mblk + wm * 32 + fr;
#pragma unroll
    for (int j = 0; j < J; ++j) {
        const int colg = nbase + wn * WN + j * 8 + fq * 2;
        const bool cv = colg < NVG;
        const float b0v = cv ? __ldg(bias + colg)     : 0.f;
        const float b1v = cv ? __ldg(bias + colg + 1) : 0.f;
        float s0 = 0.f, s1 = 0.f, q0 = 0.f, q1 = 0.f;
#pragma unroll
        for (int i = 0; i < 2; ++i) {
            float v0 = fmaxf(acc[i][j][0] + b0v, 0.f);
            float v1 = fmaxf(acc[i][j][1] + b1v, 0.f);
            float v2 = fmaxf(acc[i][j][2] + b0v, 0.f);
            float v3 = fmaxf(acc[i][j][3] + b1v, 0.f);
            if (cv) {
                *(__half2*)(OUT + (size_t)(r0 + i * 16) * OSTR + colg) =
                    __floats2half2_rn(v0, v1);
                *(__half2*)(OUT + (size_t)(r0 + i * 16 + 8) * OSTR + colg) =
                    __floats2half2_rn(v2, v3);
            }
            s0 += v0 + v2; s1 += v1 + v3;
            q0 += v0 * v0 + v2 * v2; q1 += v1 * v1 + v3 * v3;
        }
#pragma unroll
        for (int off = 4; off < 32; off <<= 1) {
            s0 += __shfl_xor_sync(0xffffffffu, s0, off);
            s1 += __shfl_xor_sync(0xffffffffu, s1, off);
            q0 += __shfl_xor_sync(0xffffffffu, q0, off);
            q1 += __shfl_xor_sync(0xffffffffu, q1, off);
        }
        if (lane < 4 && cv) {
            atomicAdd(sumP + colg, s0);
            atomicAdd(sumP + colg + 1, s1);
            atomicAdd(sqP + colg, q0);
            atomicAdd(sqP + colg + 1, q1);
        }
    }
}

// ---------------- bf16 3-term kernel for layer 3 (tiny GEMM, h2 fp16 input) ----------
__device__ __forceinline__ void split4(float4 v, uint32_t& h0, uint32_t& h1,
                                       uint32_t& l0, uint32_t& l1) {
    uint2 hi, lo;
    split4v(v, hi, lo);
    h0 = hi.x; h1 = hi.y; l0 = lo.x; l1 = lo.y;
}

__global__ void __launch_bounds__(256, 2)
gemm3_legacy(const float* __restrict__ W, const float* __restrict__ bias,
             const float* __restrict__ S, const float* __restrict__ Mn,
             float* __restrict__ OUTF)
{
    constexpr int K = 100, KS = 7, NV = 10, ASTR = 128, NSTR = 100, OSTR = 10;

    __shared__ __align__(16) uint32_t sAh[128 * 12];
    __shared__ __align__(16) uint32_t sAl[128 * 12];
    __shared__ __align__(16) uint32_t sBh[64 * 12];
    __shared__ __align__(16) uint32_t sBl[64 * 12];
    __shared__ __align__(16) float sScale[112];
    __shared__ __align__(16) float sShift[112];

    const int tid  = threadIdx.x;
    const int lane = tid & 31;
    const int wid  = tid >> 5;
    const int wm   = wid >> 1;
    const int wn   = wid & 1;
    const int mblk = blockIdx.x * 128;
    const int la_m = tid >> 2;
    const int la_c = (tid & 3) << 2;

    for (int i = tid; i < K; i += 256) { sScale[i] = g_scale2[i]; sShift[i] = g_shift2[i]; }
    __syncthreads();

    float acc[2][4][4];
#pragma unroll
    for (int i = 0; i < 2; i++)
#pragma unroll
        for (int j = 0; j < 4; j++)
#pragma unroll
            for (int c = 0; c < 4; c++) acc[i][j][c] = 0.f;

    float4 va0, va1, vb;
    auto LOADA = [&](int s, float4& o0, float4& o1) {
        const int k0 = s * 16 + la_c;
        if (k0 + 3 < K) {
            const int m0 = mblk + la_m;
            float4 h0 = h4_to_f4(*(const uint2*)(g_h2 + (size_t)m0 * ASTR + k0));
            float4 h1 = h4_to_f4(*(const uint2*)(g_h2 + (size_t)(m0 + 64) * ASTR + k0));
            float4 s0 = *(const float4*)(S + (size_t)m0 * NSTR + k0);
            float4 s1 = *(const float4*)(S + (size_t)(m0 + 64) * NSTR + k0);
            float4 q0 = *(const float4*)(Mn + (size_t)m0 * NSTR + k0);
            float4 q1 = *(const float4*)(Mn + (size_t)(m0 + 64) * NSTR + k0);
            float4 sc = *(const float4*)(sScale + k0);
            float4 sh = *(const float4*)(sShift + k0);
            o0.x = fmaf(s0.x, fmaf(sc.x, h0.x, sh.x), q0.x);
            o0.y = fmaf(s0.y, fmaf(sc.y, h0.y, sh.y), q0.y);
            o0.z = fmaf(s0.z, fmaf(sc.z, h0.z, sh.z), q0.z);
            o0.w = fmaf(s0.w, fmaf(sc.w, h0.w, sh.w), q0.w);
            o1.x = fmaf(s1.x, fmaf(sc.x, h1.x, sh.x), q1.x);
            o1.y = fmaf(s1.y, fmaf(sc.y, h1.y, sh.y), q1.y);
            o1.z = fmaf(s1.z, fmaf(sc.z, h1.z, sh.z), q1.z);
            o1.w = fmaf(s1.w, fmaf(sc.w, h1.w, sh.w), q1.w);
        } else {
            o0 = make_float4(0.f, 0.f, 0.f, 0.f);
            o1 = make_float4(0.f, 0.f, 0.f, 0.f);
        }
    };
    auto LOADB = [&](int s, float4& o) {
        const int k0 = s * 16 + la_c;
        const int n  = la_m;
        const bool ok = (n < NV) && (k0 + 3 < K);
        o = ok ? *(const float4*)(W + (size_t)n * K + k0)
               : make_float4(0.f, 0.f, 0.f, 0.f);
    };

    LOADA(0, va0, va1);
    LOADB(0, vb);

    const int r4 = lane >> 2;
    const int tg = lane & 3;

    for (int s = 0; s < KS; ++s) {
        {
            const int wbase = la_m * 12 + (la_c >> 1);
            uint32_t h0, h1, l0, l1;
            split4(va0, h0, h1, l0, l1);
            sAh[wbase] = h0; sAh[wbase + 1] = h1;
            sAl[wbase] = l0; sAl[wbase + 1] = l1;
            split4(va1, h0, h1, l0, l1);
            sAh[wbase + 768] = h0; sAh[wbase + 769] = h1;
            sAl[wbase + 768] = l0; sAl[wbase + 769] = l1;
            split4(vb, h0, h1, l0, l1);
            sBh[wbase] = h0; sBh[wbase + 1] = h1;
            sBl[wbase] = l0; sBl[wbase + 1] = l1;
        }
        __syncthreads();
        if (s + 1 < KS) { LOADA(s + 1, va0, va1); LOADB(s + 1, vb); }

        uint32_t ah[2][4], al[2][4], bh[4][2], bl[4][2];
#pragma unroll
        for (int i = 0; i < 2; i++) {
            const int base = (wm * 32 + i * 16 + r4) * 12 + tg;
            ah[i][0] = sAh[base];       ah[i][1] = sAh[base + 96];
            ah[i][2] = sAh[base + 4];   ah[i][3] = sAh[base + 100];
            al[i][0] = sAl[base];       al[i][1] = sAl[base + 96];
            al[i][2] = sAl[base + 4];   al[i][3] = sAl[base + 100];
        }
#pragma unroll
        for (int j = 0; j < 4; j++) {
            const int base = (wn * 32 + j * 8 + r4) * 12 + tg;
            bh[j][0] = sBh[base]; bh[j][1] = sBh[base + 4];
            bl[j][0] = sBl[base]; bl[j][1] = sBl[base + 4];
        }
#pragma unroll
        for (int i = 0; i < 2; i++)
#pragma unroll
            for (int j = 0; j < 4; j++) {
                mma16(acc[i][j], ah[i], bh[j]);
                mma16(acc[i][j], ah[i], bl[j]);
                mma16(acc[i][j], al[i], bh[j]);
            }
        __syncthreads();
    }

#pragma unroll
    for (int i = 0; i < 2; i++)
#pragma unroll
        for (int j = 0; j < 4; j++)
#pragma unroll
            for (int c = 0; c < 4; c++) {
                const int row = mblk + wm * 32 + i * 16 + r4 + ((c & 2) ? 8 : 0);
                const int col = wn * 32 + j * 8 + 2 * tg + (c & 1);
                if (col < NV) {
                    float v = acc[i][j][c] + __ldg(bias + col);
                    OUTF[(size_t)row * OSTR + col] = v;
                }
            }
}

// ---------------- batch statistics ----------------
__global__ void zero_stats() {
    const int t = threadIdx.x;
    if (t < 320) { g_sum1[t] = 0.f; g_sq1[t] = 0.f; }
    if (t < 128) { g_sum2[t] = 0.f; g_sq2[t] = 0.f; }
}

template <int L>
__global__ void finalize(const float* __restrict__ g, const float* __restrict__ be) {
    constexpr int NV = (L == 1) ? 300 : 100;
    const float* sumP = (L == 1) ? g_sum1 : g_sum2;
    const float* sqP  = (L == 1) ? g_sq1  : g_sq2;
    float* scP = (L == 1) ? g_scale1 : g_scale2;
    float* shP = (L == 1) ? g_shift1 : g_shift2;
    const int c = threadIdx.x;
    if (c >= NV) return;
    const float inv = 1.f / 65536.f;
    const float mean = sumP[c] * inv;
    const float var  = sqP[c] * inv - mean * mean;
    const float sc   = g[c] * rsqrtf(var + 1e-5f);
    scP[c] = sc;
    shP[c] = be[c] - sc * mean;
}

// ---------------- launch ----------------
extern "C" void kernel_launch(void* const* d_in, const int* in_sizes, int n_in,
                              void* d_out, int out_size) {
    const float* x   = (const float*)d_in[0];
    const float* W1  = (const float*)d_in[1];
    const float* b1  = (const float*)d_in[2];
    const float* g1  = (const float*)d_in[3];
    const float* be1 = (const float*)d_in[4];
    const float* s1  = (const float*)d_in[5];
    const float* m1  = (const float*)d_in[6];
    const float* W2  = (const float*)d_in[7];
    const float* b2  = (const float*)d_in[8];
    const float* g2  = (const float*)d_in[9];
    const float* be2 = (const float*)d_in[10];
    const float* s2  = (const float*)d_in[11];
    const float* m2  = (const float*)d_in[12];
    const float* W3  = (const float*)d_in[13];
    const float* b3  = (const float*)d_in[14];
    float* out = (float*)d_out;

    const int SM1 = 2 * 5120 + 2 * (160 * 20 * 4);              // 35840
    const int SM2 = 2 * 5120 + 2 * (128 * 20 * 4) + 2560;       // 33280
    cudaFuncSetAttribute(tc_gemm<1>, cudaFuncAttributeMaxDynamicSharedMemorySize, SM1);
    cudaFuncSetAttribute(tc_gemm<2>, cudaFuncAttributeMaxDynamicSharedMemorySize, SM2);

    split_w1<<<1040, 256>>>(W1);
    split_w2<<<160, 256>>>(W2);
    zero_stats<<<1, 320>>>();
    tc_gemm<1><<<dim3(1024, 2), 128, SM1>>>(x, b1, nullptr, nullptr);
    finalize<1><<<1, 320>>>(g1, be1);
    tc_gemm<2><<<1024, 256, SM2>>>(nullptr, b2, s1, m1);
    finalize<2><<<1, 128>>>(g2, be2);
    gemm3_legacy<<<512, 256>>>(W3, b3, s2, m2, out);
}

// round 16
// speedup vs baseline: 1.1520x; 1.1520x over previous
#include <cuda_runtime.h>
#include <cuda_bf16.h>
#include <cuda_fp16.h>
#include <cstdint>

#define NBATCH 65536

// ---------------- static scratch (no runtime allocation) ----------------
__device__ __align__(16) __half g_h1[(size_t)NBATCH * 320];
__device__ __align__(16) __half g_h2[(size_t)NBATCH * 128];
__device__ float g_sum1[320], g_sq1[320], g_scale1[320], g_shift1[320];
__device__ float g_sum2[128], g_sq2[128], g_scale2[128], g_shift2[128];
__device__ __align__(16) __half gW1h[320 * 832];
__device__ __align__(16) __half gW2h[128 * 320];

// ---------------- helpers ----------------
__device__ __forceinline__ uint32_t smem_u32(const void* p) {
    uint32_t a;
    asm("{ .reg .u64 t; cvta.to.shared.u64 t, %1; cvt.u32.u64 %0, t; }" : "=r"(a) : "l"(p));
    return a;
}
__device__ __forceinline__ void cpa16(uint32_t dst, const void* src) {
    asm volatile("cp.async.cg.shared.global [%0], [%1], 16;" :: "r"(dst), "l"(src));
}
#define CP_COMMIT() asm volatile("cp.async.commit_group;" ::: "memory")
#define CP_WAIT0()  asm volatile("cp.async.wait_group 0;" ::: "memory")

__device__ __forceinline__ void mma16h(float* c, const uint32_t* a, const uint32_t* b) {
    asm volatile(
        "mma.sync.aligned.m16n8k16.row.col.f32.f16.f16.f32 "
        "{%0,%1,%2,%3},{%4,%5,%6,%7},{%8,%9},{%0,%1,%2,%3};\n"
        : "+f"(c[0]), "+f"(c[1]), "+f"(c[2]), "+f"(c[3])
        : "r"(a[0]), "r"(a[1]), "r"(a[2]), "r"(a[3]), "r"(b[0]), "r"(b[1]));
}
__device__ __forceinline__ void mma16(float* c, const uint32_t* a, const uint32_t* b) {
    asm volatile(
        "mma.sync.aligned.m16n8k16.row.col.f32.bf16.bf16.f32 "
        "{%0,%1,%2,%3},{%4,%5,%6,%7},{%8,%9},{%0,%1,%2,%3};\n"
        : "+f"(c[0]), "+f"(c[1]), "+f"(c[2]), "+f"(c[3])
        : "r"(a[0]), "r"(a[1]), "r"(a[2]), "r"(a[3]), "r"(b[0]), "r"(b[1]));
}

__device__ __forceinline__ void ldsm4(uint32_t a, uint32_t& r0, uint32_t& r1,
                                      uint32_t& r2, uint32_t& r3) {
    asm volatile("ldmatrix.sync.aligned.m8n8.x4.shared.b16 {%0,%1,%2,%3}, [%4];"
                 : "=r"(r0), "=r"(r1), "=r"(r2), "=r"(r3) : "r"(a));
}

// fp16 convert (single term)
__device__ __forceinline__ void conv4h(float4 v, uint2& hi) {
    __half2 H0 = __halves2half2(__float2half_rn(v.x), __float2half_rn(v.y));
    __half2 H1 = __halves2half2(__float2half_rn(v.z), __float2half_rn(v.w));
    hi.x = *reinterpret_cast<uint32_t*>(&H0);
    hi.y = *reinterpret_cast<uint32_t*>(&H1);
}
__device__ __forceinline__ float4 h4_to_f4(uint2 u) {
    __half2 a = *reinterpret_cast<__half2*>(&u.x);
    __half2 b = *reinterpret_cast<__half2*>(&u.y);
    float2 fa = __half22float2(a), fb = __half22float2(b);
    return make_float4(fa.x, fa.y, fb.x, fb.y);
}
// bf16 split (layer 3)
__device__ __forceinline__ void split4v(float4 v, uint2& hi, uint2& lo) {
    __nv_bfloat16 ax = __float2bfloat16(v.x), ay = __float2bfloat16(v.y);
    __nv_bfloat16 az = __float2bfloat16(v.z), aw = __float2bfloat16(v.w);
    float rx = v.x - __bfloat162float(ax), ry = v.y - __bfloat162float(ay);
    float rz = v.z - __bfloat162float(az), rw = v.w - __bfloat162float(aw);
    __nv_bfloat162 H0 = __halves2bfloat162(ax, ay), H1 = __halves2bfloat162(az, aw);
    __nv_bfloat162 L0 = __halves2bfloat162(__float2bfloat16(rx), __float2bfloat16(ry));
    __nv_bfloat162 L1 = __halves2bfloat162(__float2bfloat16(rz), __float2bfloat16(rw));
    hi.x = *reinterpret_cast<uint32_t*>(&H0); hi.y = *reinterpret_cast<uint32_t*>(&H1);
    lo.x = *reinterpret_cast<uint32_t*>(&L0); lo.y = *reinterpret_cast<uint32_t*>(&L1);
}

// ---------------- weight pre-convert (fp16, zero padded) + stats zeroing ------------
__global__ void split_w1(const float* __restrict__ W1) {
    if (blockIdx.x == 0) {
        for (int i = threadIdx.x; i < 320; i += 256) { g_sum1[i] = 0.f; g_sq1[i] = 0.f; }
        for (int i = threadIdx.x; i < 128; i += 256) { g_sum2[i] = 0.f; g_sq2[i] = 0.f; }
    }
    int idx = blockIdx.x * 256 + threadIdx.x;
    if (idx >= 320 * 832) return;
    int n = idx / 832, k = idx % 832;
    float v = (n < 300 && k < 784) ? W1[n * 784 + k] : 0.f;
    gW1h[idx] = __float2half_rn(v);
}
__global__ void split_w2(const float* __restrict__ W2) {
    int idx = blockIdx.x * 256 + threadIdx.x;
    if (idx >= 128 * 320) return;
    int n = idx / 320, k = idx % 320;
    float v = (n < 100 && k < 300) ? W2[n * 300 + k] : 0.f;
    gW2h[idx] = __float2half_rn(v);
}

// ---------------- fused GEMM (1-term fp16, single N-pass, K-chunk 32) ----------------
// MODE 1: h1 = relu(x @ W1^T + b1), fused column stats   [K=784, CTA 64x320, J=10]
// MODE 2: h2 = relu((s1*(sc1*h1+sh1)+m1) @ W2^T + b2), fused stats [K=300, CTA 64x128, J=4]
template <int MODE>
__global__ void __launch_bounds__(256, 2)
tc_gemm(const float* __restrict__ X, const float* __restrict__ bias,
        const float* __restrict__ S, const float* __restrict__ Mn)
{
    constexpr int NT   = (MODE == 1) ? 320 : 128;   // CTA N tile (full N)
    constexpr int WN   = NT / 4;                    // warp N tile (80 / 32)
    constexpr int J    = WN / 8;                    // n-frags per warp (10 / 4)
    constexpr int JP   = J / 2;                     // ldsm4 pairs (5 / 2)
    constexpr int KV   = (MODE == 1) ? 784 : 300;
    constexpr int KSTG = (MODE == 1) ? 25 : 10;     // K chunks of 32 (W zero-padded)
    constexpr int OSTR = (MODE == 1) ? 320 : 128;
    constexpr int WSTR = (MODE == 1) ? 832 : 320;
    constexpr int NVG  = (MODE == 1) ? 300 : 100;
    constexpr int PIT  = 20;                        // words per row (80 B)
    constexpr int ABUF = 64 * PIT * 4;              // 5120 B per buf
    constexpr int BBUF = NT * PIT * 4;              // 25600 / 10240 per buf
    constexpr int OFF_B  = 2 * ABUF;
    constexpr int OFF_SC = OFF_B + 2 * BBUF;
    constexpr int CH = NT * 4;                      // 16B chunks per stage

    extern __shared__ __align__(16) char smc[];
    const uint32_t sb = smem_u32(smc);

    const int tid  = threadIdx.x;
    const int lane = tid & 31;
    const int wid  = tid >> 5;
    const int wm   = wid >> 2;          // 0..1
    const int wn   = wid & 3;           // 0..3
    const int mblk = blockIdx.x * 64;
    const int arow = tid >> 2;          // 0..63
    const int af4  = tid & 3;           // 0..3

    const __half* Wh = (MODE == 1) ? gW1h : gW2h;
    __half* OUT = (MODE == 1) ? g_h1 : g_h2;
    float* sumP = (MODE == 1) ? g_sum1 : g_sum2;
    float* sqP  = (MODE == 1) ? g_sq1  : g_sq2;

    float* sScale = (float*)(smc + OFF_SC);
    float* sShift = (float*)(smc + OFF_SC + 1280);
    if (MODE == 2) {
        for (int i = tid; i < KV; i += 256) {
            sScale[i] = g_scale1[i];
            sShift[i] = g_shift1[i];
        }
        __syncthreads();
    }

    float acc[2][J][4];
#pragma unroll
    for (int i = 0; i < 2; i++)
#pragma unroll
        for (int j = 0; j < J; j++)
#pragma unroll
            for (int c = 0; c < 4; c++) acc[i][j][c] = 0.f;

    float4 va[2];

    auto LDA = [&](int c) {
        const int k0 = c * 32 + af4 * 4;
        const size_t m = (size_t)(mblk + arow);
        if (MODE == 1) {
#pragma unroll
            for (int q = 0; q < 2; ++q) {
                const int kk = k0 + q * 16;
                va[q] = (kk + 3 < KV) ? *(const float4*)(X + m * 784 + kk)
                                      : make_float4(0.f, 0.f, 0.f, 0.f);
            }
        } else {
#pragma unroll
            for (int q = 0; q < 2; ++q) {
                const int kk = k0 + q * 16;
                float4 o;
                if (kk + 3 < KV) {
                    uint2 raw = *(const uint2*)(g_h1 + m * 320 + kk);
                    float4 h  = h4_to_f4(raw);
                    float4 s  = *(const float4*)(S + m * 300 + kk);
                    float4 q2 = *(const float4*)(Mn + m * 300 + kk);
                    float4 sc = *(const float4*)(sScale + kk);
                    float4 sh = *(const float4*)(sShift + kk);
                    o.x = fmaf(s.x, fmaf(sc.x, h.x, sh.x), q2.x);
                    o.y = fmaf(s.y, fmaf(sc.y, h.y, sh.y), q2.y);
                    o.z = fmaf(s.z, fmaf(sc.z, h.z, sh.z), q2.z);
                    o.w = fmaf(s.w, fmaf(sc.w, h.w, sh.w), q2.w);
                } else o = make_float4(0.f, 0.f, 0.f, 0.f);
                va[q] = o;
            }
        }
    };

    auto STSA = [&](int buf) {
        uint32_t* pH = (uint32_t*)(smc + buf * ABUF);
#pragma unroll
        for (int q = 0; q < 2; ++q) {
            uint2 hi;
            conv4h(va[q], hi);
            const int b0 = arow * PIT + af4 * 2 + q * 8;
            *(uint2*)(pH + b0) = hi;
        }
    };

    auto CPB = [&](int c, int buf) {
        constexpr int ITER = CH / 256;   // 5 or 2
#pragma unroll
        for (int i = 0; i < ITER; ++i) {
            const int it = tid + i * 256;
            const int r  = it >> 2, c4 = it & 3;
            const __half* src = Wh + (size_t)r * WSTR + c * 32 + c4 * 8;
            const uint32_t dst = sb + OFF_B + buf * BBUF + (r * PIT + c4 * 4) * 4;
            cpa16(dst, src);
        }
        CP_COMMIT();
    };

    // ldmatrix lane addresses (pitch 20 words = 80 B, conflict-free)
    const uint32_t aBase = sb + ((uint32_t)(wm * 32 + (lane & 15)) * PIT + ((lane >> 4) << 2)) * 4;
    const uint32_t bBase = sb + OFF_B +
        ((uint32_t)(wn * WN + ((lane >> 4) << 3) + (lane & 7)) * PIT + (((lane >> 3) & 1) << 2)) * 4;
    constexpr uint32_t AROW16 = 16 * PIT * 4;    // 1280
    constexpr uint32_t BROW16 = 16 * PIT * 4;    // 1280 per j-pair

    // prologue
    LDA(0);
    CPB(0, 0);
    STSA(0);
    CP_WAIT0();
    __syncthreads();

    const int fr = lane >> 2;   // 0..7
    const int fq = lane & 3;    // 0..3

    for (int c = 0; c < KSTG; ++c) {
        const int cur = c & 1;
        if (c + 1 < KSTG) { LDA(c + 1); CPB(c + 1, cur ^ 1); }

        const uint32_t aOff = (uint32_t)cur * ABUF;
        const uint32_t bOff = (uint32_t)cur * BBUF;

#pragma unroll
        for (int kk = 0; kk < 2; ++kk) {
            const uint32_t kb = kk * 32;   // 16 fp16 = 32 bytes per kk
            uint32_t ah0[4], ah1[4];
            ldsm4(aBase + aOff + kb,          ah0[0], ah0[1], ah0[2], ah0[3]);
            ldsm4(aBase + aOff + AROW16 + kb, ah1[0], ah1[1], ah1[2], ah1[3]);
#pragma unroll
            for (int jp = 0; jp < JP; ++jp) {
                uint32_t b4[4];   // two n-frags, JIT load (4 live regs)
                ldsm4(bBase + bOff + (uint32_t)jp * BROW16 + kb,
                      b4[0], b4[1], b4[2], b4[3]);
                mma16h(acc[0][2 * jp],     ah0, b4);
                mma16h(acc[1][2 * jp],     ah1, b4);
                mma16h(acc[0][2 * jp + 1], ah0, b4 + 2);
                mma16h(acc[1][2 * jp + 1], ah1, b4 + 2);
            }
        }

        if (c + 1 < KSTG) { STSA(cur ^ 1); CP_WAIT0(); }
        __syncthreads();
    }

    // ---- epilogue: bias + relu + fp16 store + fused column stats ----
    const int r0 = mblk + wm * 32 + fr;
#pragma unroll
    for (int j = 0; j < J; ++j) {
        const int colg = wn * WN + j * 8 + fq * 2;
        const bool cv = colg < NVG;
        const float b0v = cv ? __ldg(bias + colg)     : 0.f;
        const float b1v = cv ? __ldg(bias + colg + 1) : 0.f;
        float s0 = 0.f, s1 = 0.f, q0 = 0.f, q1 = 0.f;
#pragma unroll
        for (int i = 0; i < 2; ++i) {
            float v0 = fmaxf(acc[i][j][0] + b0v, 0.f);
            float v1 = fmaxf(acc[i][j][1] + b1v, 0.f);
            float v2 = fmaxf(acc[i][j][2] + b0v, 0.f);
            float v3 = fmaxf(acc[i][j][3] + b1v, 0.f);
            if (cv) {
                *(__half2*)(OUT + (size_t)(r0 + i * 16) * OSTR + colg) =
                    __floats2half2_rn(v0, v1);
                *(__half2*)(OUT + (size_t)(r0 + i * 16 + 8) * OSTR + colg) =
                    __floats2half2_rn(v2, v3);
            }
            s0 += v0 + v2; s1 += v1 + v3;
            q0 += v0 * v0 + v2 * v2; q1 += v1 * v1 + v3 * v3;
        }
#pragma unroll
        for (int off = 4; off < 32; off <<= 1) {
            s0 += __shfl_xor_sync(0xffffffffu, s0, off);
            s1 += __shfl_xor_sync(0xffffffffu, s1, off);
            q0 += __shfl_xor_sync(0xffffffffu, q0, off);
            q1 += __shfl_xor_sync(0xffffffffu, q1, off);
        }
        if (lane < 4 && cv) {
            atomicAdd(sumP + colg, s0);
            atomicAdd(sumP + colg + 1, s1);
            atomicAdd(sqP + colg, q0);
            atomicAdd(sqP + colg + 1, q1);
        }
    }
}

// ---------------- bf16 3-term kernel for layer 3 (tiny GEMM, h2 fp16 input) ----------
__device__ __forceinline__ void split4(float4 v, uint32_t& h0, uint32_t& h1,
                                       uint32_t& l0, uint32_t& l1) {
    uint2 hi, lo;
    split4v(v, hi, lo);
    h0 = hi.x; h1 = hi.y; l0 = lo.x; l1 = lo.y;
}

__global__ void __launch_bounds__(256, 2)
gemm3_legacy(const float* __restrict__ W, const float* __restrict__ bias,
             const float* __restrict__ S, const float* __restrict__ Mn,
             float* __restrict__ OUTF)
{
    constexpr int K = 100, KS = 7, NV = 10, ASTR = 128, NSTR = 100, OSTR = 10;

    __shared__ __align__(16) uint32_t sAh[128 * 12];
    __shared__ __align__(16) uint32_t sAl[128 * 12];
    __shared__ __align__(16) uint32_t sBh[64 * 12];
    __shared__ __align__(16) uint32_t sBl[64 * 12];
    __shared__ __align__(16) float sScale[112];
    __shared__ __align__(16) float sShift[112];

    const int tid  = threadIdx.x;
    const int lane = tid & 31;
    const int wid  = tid >> 5;
    const int wm   = wid >> 1;
    const int wn   = wid & 1;
    const int mblk = blockIdx.x * 128;
    const int la_m = tid >> 2;
    const int la_c = (tid & 3) << 2;

    for (int i = tid; i < K; i += 256) { sScale[i] = g_scale2[i]; sShift[i] = g_shift2[i]; }
    __syncthreads();

    float acc[2][4][4];
#pragma unroll
    for (int i = 0; i < 2; i++)
#pragma unroll
        for (int j = 0; j < 4; j++)
#pragma unroll
            for (int c = 0; c < 4; c++) acc[i][j][c] = 0.f;

    float4 va0, va1, vb;
    auto LOADA = [&](int s, float4& o0, float4& o1) {
        const int k0 = s * 16 + la_c;
        if (k0 + 3 < K) {
            const int m0 = mblk + la_m;
            float4 h0 = h4_to_f4(*(const uint2*)(g_h2 + (size_t)m0 * ASTR + k0));
            float4 h1 = h4_to_f4(*(const uint2*)(g_h2 + (size_t)(m0 + 64) * ASTR + k0));
            float4 s0 = *(const float4*)(S + (size_t)m0 * NSTR + k0);
            float4 s1 = *(const float4*)(S + (size_t)(m0 + 64) * NSTR + k0);
            float4 q0 = *(const float4*)(Mn + (size_t)m0 * NSTR + k0);
            float4 q1 = *(const float4*)(Mn + (size_t)(m0 + 64) * NSTR + k0);
            float4 sc = *(const float4*)(sScale + k0);
            float4 sh = *(const float4*)(sShift + k0);
            o0.x = fmaf(s0.x, fmaf(sc.x, h0.x, sh.x), q0.x);
            o0.y = fmaf(s0.y, fmaf(sc.y, h0.y, sh.y), q0.y);
            o0.z = fmaf(s0.z, fmaf(sc.z, h0.z, sh.z), q0.z);
            o0.w = fmaf(s0.w, fmaf(sc.w, h0.w, sh.w), q0.w);
            o1.x = fmaf(s1.x, fmaf(sc.x, h1.x, sh.x), q1.x);
            o1.y = fmaf(s1.y, fmaf(sc.y, h1.y, sh.y), q1.y);
            o1.z = fmaf(s1.z, fmaf(sc.z, h1.z, sh.z), q1.z);
            o1.w = fmaf(s1.w, fmaf(sc.w, h1.w, sh.w), q1.w);
        } else {
            o0 = make_float4(0.f, 0.f, 0.f, 0.f);
            o1 = make_float4(0.f, 0.f, 0.f, 0.f);
        }
    };
    auto LOADB = [&](int s, float4& o) {
        const int k0 = s * 16 + la_c;
        const int n  = la_m;
        const bool ok = (n < NV) && (k0 + 3 < K);
        o = ok ? *(const float4*)(W + (size_t)n * K + k0)
               : make_float4(0.f, 0.f, 0.f, 0.f);
    };

    LOADA(0, va0, va1);
    LOADB(0, vb);

    const int r4 = lane >> 2;
    const int tg = lane & 3;

    for (int s = 0; s < KS; ++s) {
        {
            const int wbase = la_m * 12 + (la_c >> 1);
            uint32_t h0, h1, l0, l1;
            split4(va0, h0, h1, l0, l1);
            sAh[wbase] = h0; sAh[wbase + 1] = h1;
            sAl[wbase] = l0; sAl[wbase + 1] = l1;
            split4(va1, h0, h1, l0, l1);
            sAh[wbase + 768] = h0; sAh[wbase + 769] = h1;
            sAl[wbase + 768] = l0; sAl[wbase + 769] = l1;
            split4(vb, h0, h1, l0, l1);
            sBh[wbase] = h0; sBh[wbase + 1] = h1;
            sBl[wbase] = l0; sBl[wbase + 1] = l1;
        }
        __syncthreads();
        if (s + 1 < KS) { LOADA(s + 1, va0, va1); LOADB(s + 1, vb); }

        uint32_t ah[2][4], al[2][4], bh[4][2], bl[4][2];
#pragma unroll
        for (int i = 0; i < 2; i++) {
            const int base = (wm * 32 + i * 16 + r4) * 12 + tg;
            ah[i][0] = sAh[base];       ah[i][1] = sAh[base + 96];
            ah[i][2] = sAh[base + 4];   ah[i][3] = sAh[base + 100];
            al[i][0] = sAl[base];       al[i][1] = sAl[base + 96];
            al[i][2] = sAl[base + 4];   al[i][3] = sAl[base + 100];
        }
#pragma unroll
        for (int j = 0; j < 4; j++) {
            const int base = (wn * 32 + j * 8 + r4) * 12 + tg;
            bh[j][0] = sBh[base]; bh[j][1] = sBh[base + 4];
            bl[j][0] = sBl[base]; bl[j][1] = sBl[base + 4];
        }
#pragma unroll
        for (int i = 0; i < 2; i++)
#pragma unroll
            for (int j = 0; j < 4; j++) {
                mma16(acc[i][j], ah[i], bh[j]);
                mma16(acc[i][j], ah[i], bl[j]);
                mma16(acc[i][j], al[i], bh[j]);
            }
        __syncthreads();
    }

#pragma unroll
    for (int i = 0; i < 2; i++)
#pragma unroll
        for (int j = 0; j < 4; j++)
#pragma unroll
            for (int c = 0; c < 4; c++) {
                const int row = mblk + wm * 32 + i * 16 + r4 + ((c & 2) ? 8 : 0);
                const int col = wn * 32 + j * 8 + 2 * tg + (c & 1);
                if (col < NV) {
                    float v = acc[i][j][c] + __ldg(bias + col);
                    OUTF[(size_t)row * OSTR + col] = v;
                }
            }
}

// ---------------- batch statistics finalize ----------------
template <int L>
__global__ void finalize(const float* __restrict__ g, const float* __restrict__ be) {
    constexpr int NV = (L == 1) ? 300 : 100;
    const float* sumP = (L == 1) ? g_sum1 : g_sum2;
    const float* sqP  = (L == 1) ? g_sq1  : g_sq2;
    float* scP = (L == 1) ? g_scale1 : g_scale2;
    float* shP = (L == 1) ? g_shift1 : g_shift2;
    const int c = threadIdx.x;
    if (c >= NV) return;
    const float inv = 1.f / 65536.f;
    const float mean = sumP[c] * inv;
    const float var  = sqP[c] * inv - mean * mean;
    const float sc   = g[c] * rsqrtf(var + 1e-5f);
    scP[c] = sc;
    shP[c] = be[c] - sc * mean;
}

// ---------------- launch ----------------
extern "C" void kernel_launch(void* const* d_in, const int* in_sizes, int n_in,
                              void* d_out, int out_size) {
    const float* x   = (const float*)d_in[0];
    const float* W1  = (const float*)d_in[1];
    const float* b1  = (const float*)d_in[2];
    const float* g1  = (const float*)d_in[3];
    const float* be1 = (const float*)d_in[4];
    const float* s1  = (const float*)d_in[5];
    const float* m1  = (const float*)d_in[6];
    const float* W2  = (const float*)d_in[7];
    const float* b2  = (const float*)d_in[8];
    const float* g2  = (const float*)d_in[9];
    const float* be2 = (const float*)d_in[10];
    const float* s2  = (const float*)d_in[11];
    const float* m2  = (const float*)d_in[12];
    const float* W3  = (const float*)d_in[13];
    const float* b3  = (const float*)d_in[14];
    float* out = (float*)d_out;

    const int SM1 = 2 * 5120 + 2 * (320 * 20 * 4);              // 61440
    const int SM2 = 2 * 5120 + 2 * (128 * 20 * 4) + 2560;       // 33280
    cudaFuncSetAttribute(tc_gemm<1>, cudaFuncAttributeMaxDynamicSharedMemorySize, SM1);
    cudaFuncSetAttribute(tc_gemm<2>, cudaFuncAttributeMaxDynamicSharedMemorySize, SM2);

    split_w1<<<1040, 256>>>(W1);
    split_w2<<<160, 256>>>(W2);
    tc_gemm<1><<<1024, 256, SM1>>>(x, b1, nullptr, nullptr);
    finalize<1><<<1, 320>>>(g1, be1);
    tc_gemm<2><<<1024, 256, SM2>>>(nullptr, b2, s1, m1);
    finalize<2><<<1, 128>>>(g2, be2);
    gemm3_legacy<<<512, 256>>>(W3, b3, s2, m2, out);
}

// round 17
// speedup vs baseline: 1.2323x; 1.0696x over previous
#include <cuda_runtime.h>
#include <cuda_bf16.h>
#include <cuda_fp16.h>
#include <cstdint>

#define NBATCH 65536

// ---------------- static scratch (no runtime allocation) ----------------
__device__ __align__(16) __half g_h1[(size_t)NBATCH * 320];
__device__ __align__(16) __half g_h2[(size_t)NBATCH * 128];
__device__ float g_sum1[320], g_sq1[320];
__device__ float g_sum2[128], g_sq2[128];
__device__ __align__(16) __half gW1h[320 * 832];
__device__ __align__(16) __half gW2h[128 * 320];

// ---------------- helpers ----------------
__device__ __forceinline__ uint32_t smem_u32(const void* p) {
    uint32_t a;
    asm("{ .reg .u64 t; cvta.to.shared.u64 t, %1; cvt.u32.u64 %0, t; }" : "=r"(a) : "l"(p));
    return a;
}
__device__ __forceinline__ void cpa16(uint32_t dst, const void* src) {
    asm volatile("cp.async.cg.shared.global [%0], [%1], 16;" :: "r"(dst), "l"(src));
}
#define CP_COMMIT() asm volatile("cp.async.commit_group;" ::: "memory")
#define CP_WAIT0()  asm volatile("cp.async.wait_group 0;" ::: "memory")

__device__ __forceinline__ void mma16h(float* c, const uint32_t* a, const uint32_t* b) {
    asm volatile(
        "mma.sync.aligned.m16n8k16.row.col.f32.f16.f16.f32 "
        "{%0,%1,%2,%3},{%4,%5,%6,%7},{%8,%9},{%0,%1,%2,%3};\n"
        : "+f"(c[0]), "+f"(c[1]), "+f"(c[2]), "+f"(c[3])
        : "r"(a[0]), "r"(a[1]), "r"(a[2]), "r"(a[3]), "r"(b[0]), "r"(b[1]));
}
__device__ __forceinline__ void mma16(float* c, const uint32_t* a, const uint32_t* b) {
    asm volatile(
        "mma.sync.aligned.m16n8k16.row.col.f32.bf16.bf16.f32 "
        "{%0,%1,%2,%3},{%4,%5,%6,%7},{%8,%9},{%0,%1,%2,%3};\n"
        : "+f"(c[0]), "+f"(c[1]), "+f"(c[2]), "+f"(c[3])
        : "r"(a[0]), "r"(a[1]), "r"(a[2]), "r"(a[3]), "r"(b[0]), "r"(b[1]));
}

__device__ __forceinline__ void ldsm4(uint32_t a, uint32_t& r0, uint32_t& r1,
                                      uint32_t& r2, uint32_t& r3) {
    asm volatile("ldmatrix.sync.aligned.m8n8.x4.shared.b16 {%0,%1,%2,%3}, [%4];"
                 : "=r"(r0), "=r"(r1), "=r"(r2), "=r"(r3) : "r"(a));
}

// fp16 convert (single term)
__device__ __forceinline__ void conv4h(float4 v, uint2& hi) {
    __half2 H0 = __halves2half2(__float2half_rn(v.x), __float2half_rn(v.y));
    __half2 H1 = __halves2half2(__float2half_rn(v.z), __float2half_rn(v.w));
    hi.x = *reinterpret_cast<uint32_t*>(&H0);
    hi.y = *reinterpret_cast<uint32_t*>(&H1);
}
__device__ __forceinline__ float4 h4_to_f4(uint2 u) {
    __half2 a = *reinterpret_cast<__half2*>(&u.x);
    __half2 b = *reinterpret_cast<__half2*>(&u.y);
    float2 fa = __half22float2(a), fb = __half22float2(b);
    return make_float4(fa.x, fa.y, fb.x, fb.y);
}
// bf16 split (layer 3)
__device__ __forceinline__ void split4v(float4 v, uint2& hi, uint2& lo) {
    __nv_bfloat16 ax = __float2bfloat16(v.x), ay = __float2bfloat16(v.y);
    __nv_bfloat16 az = __float2bfloat16(v.z), aw = __float2bfloat16(v.w);
    float rx = v.x - __bfloat162float(ax), ry = v.y - __bfloat162float(ay);
    float rz = v.z - __bfloat162float(az), rw = v.w - __bfloat162float(aw);
    __nv_bfloat162 H0 = __halves2bfloat162(ax, ay), H1 = __halves2bfloat162(az, aw);
    __nv_bfloat162 L0 = __halves2bfloat162(__float2bfloat16(rx), __float2bfloat16(ry));
    __nv_bfloat162 L1 = __halves2bfloat162(__float2bfloat16(rz), __float2bfloat16(rw));
    hi.x = *reinterpret_cast<uint32_t*>(&H0); hi.y = *reinterpret_cast<uint32_t*>(&H1);
    lo.x = *reinterpret_cast<uint32_t*>(&L0); lo.y = *reinterpret_cast<uint32_t*>(&L1);
}

// scale/shift from raw batch stats (per-CTA, deterministic)
__device__ __forceinline__ void bn_coeff(float sum, float sq, float g, float be,
                                         float& sc, float& sh) {
    const float inv = 1.f / 65536.f;
    const float mean = sum * inv;
    const float var  = sq * inv - mean * mean;
    sc = g * rsqrtf(var + 1e-5f);
    sh = be - sc * mean;
}

// ---------------- weight pre-convert (fp16, zero padded) + stats zeroing ------------
// blocks [0,1040): W1 ; blocks [1040,1200): W2 ; block 0 also zeroes stats
__global__ void split_w(const float* __restrict__ W1, const float* __restrict__ W2) {
    if (blockIdx.x == 0) {
        for (int i = threadIdx.x; i < 320; i += 256) { g_sum1[i] = 0.f; g_sq1[i] = 0.f; }
        for (int i = threadIdx.x; i < 128; i += 256) { g_sum2[i] = 0.f; g_sq2[i] = 0.f; }
    }
    if (blockIdx.x < 1040) {
        int idx = blockIdx.x * 256 + threadIdx.x;
        if (idx >= 320 * 832) return;
        int n = idx / 832, k = idx % 832;
        float v = (n < 300 && k < 784) ? W1[n * 784 + k] : 0.f;
        gW1h[idx] = __float2half_rn(v);
    } else {
        int idx = (blockIdx.x - 1040) * 256 + threadIdx.x;
        if (idx >= 128 * 320) return;
        int n = idx / 320, k = idx % 320;
        float v = (n < 100 && k < 300) ? W2[n * 300 + k] : 0.f;
        gW2h[idx] = __float2half_rn(v);
    }
}

// ---------------- fused GEMM (1-term fp16, single N-pass, K-chunk 32) ----------------
// MODE 1: h1 = relu(x @ W1^T + b1), fused column stats   [K=784, CTA 64x320, J=10]
// MODE 2: h2 = relu((s1*(sc1*h1+sh1)+m1) @ W2^T + b2), fused stats [K=300, CTA 64x128, J=4]
//         (BN coefficients computed per-CTA from g_sum1/g_sq1 — no finalize kernel)
template <int MODE>
__global__ void __launch_bounds__(256, 2)
tc_gemm(const float* __restrict__ X, const float* __restrict__ bias,
        const float* __restrict__ S, const float* __restrict__ Mn,
        const float* __restrict__ G, const float* __restrict__ BE)
{
    constexpr int NT   = (MODE == 1) ? 320 : 128;   // CTA N tile (full N)
    constexpr int WN   = NT / 4;                    // warp N tile (80 / 32)
    constexpr int J    = WN / 8;                    // n-frags per warp (10 / 4)
    constexpr int JP   = J / 2;                     // ldsm4 pairs (5 / 2)
    constexpr int KV   = (MODE == 1) ? 784 : 300;
    constexpr int KSTG = (MODE == 1) ? 25 : 10;     // K chunks of 32 (W zero-padded)
    constexpr int OSTR = (MODE == 1) ? 320 : 128;
    constexpr int WSTR = (MODE == 1) ? 832 : 320;
    constexpr int NVG  = (MODE == 1) ? 300 : 100;
    constexpr int PIT  = 20;                        // words per row (80 B)
    constexpr int ABUF = 64 * PIT * 4;              // 5120 B per buf
    constexpr int BBUF = NT * PIT * 4;              // 25600 / 10240 per buf
    constexpr int OFF_B  = 2 * ABUF;
    constexpr int OFF_SC = OFF_B + 2 * BBUF;
    constexpr int CH = NT * 4;                      // 16B chunks per stage

    extern __shared__ __align__(16) char smc[];
    const uint32_t sb = smem_u32(smc);

    const int tid  = threadIdx.x;
    const int lane = tid & 31;
    const int wid  = tid >> 5;
    const int wm   = wid >> 2;          // 0..1
    const int wn   = wid & 3;           // 0..3
    const int mblk = blockIdx.x * 64;
    const int arow = tid >> 2;          // 0..63
    const int af4  = tid & 3;           // 0..3

    const __half* Wh = (MODE == 1) ? gW1h : gW2h;
    __half* OUT = (MODE == 1) ? g_h1 : g_h2;
    float* sumP = (MODE == 1) ? g_sum1 : g_sum2;
    float* sqP  = (MODE == 1) ? g_sq1  : g_sq2;

    float* sScale = (float*)(smc + OFF_SC);
    float* sShift = (float*)(smc + OFF_SC + 1280);
    if (MODE == 2) {
        for (int i = tid; i < KV; i += 256) {
            float sc, sh;
            bn_coeff(g_sum1[i], g_sq1[i], G[i], BE[i], sc, sh);
            sScale[i] = sc;
            sShift[i] = sh;
        }
        __syncthreads();
    }

    float acc[2][J][4];
#pragma unroll
    for (int i = 0; i < 2; i++)
#pragma unroll
        for (int j = 0; j < J; j++)
#pragma unroll
            for (int c = 0; c < 4; c++) acc[i][j][c] = 0.f;

    float4 va[2];

    auto LDA = [&](int c) {
        const int k0 = c * 32 + af4 * 4;
        const size_t m = (size_t)(mblk + arow);
        if (MODE == 1) {
#pragma unroll
            for (int q = 0; q < 2; ++q) {
                const int kk = k0 + q * 16;
                va[q] = (kk + 3 < KV) ? *(const float4*)(X + m * 784 + kk)
                                      : make_float4(0.f, 0.f, 0.f, 0.f);
            }
        } else {
#pragma unroll
            for (int q = 0; q < 2; ++q) {
                const int kk = k0 + q * 16;
                float4 o;
                if (kk + 3 < KV) {
                    uint2 raw = *(const uint2*)(g_h1 + m * 320 + kk);
                    float4 h  = h4_to_f4(raw);
                    float4 s  = *(const float4*)(S + m * 300 + kk);
                    float4 q2 = *(const float4*)(Mn + m * 300 + kk);
                    float4 sc = *(const float4*)(sScale + kk);
                    float4 sh = *(const float4*)(sShift + kk);
                    o.x = fmaf(s.x, fmaf(sc.x, h.x, sh.x), q2.x);
                    o.y = fmaf(s.y, fmaf(sc.y, h.y, sh.y), q2.y);
                    o.z = fmaf(s.z, fmaf(sc.z, h.z, sh.z), q2.z);
                    o.w = fmaf(s.w, fmaf(sc.w, h.w, sh.w), q2.w);
                } else o = make_float4(0.f, 0.f, 0.f, 0.f);
                va[q] = o;
            }
        }
    };

    auto STSA = [&](int buf) {
        uint32_t* pH = (uint32_t*)(smc + buf * ABUF);
#pragma unroll
        for (int q = 0; q < 2; ++q) {
            uint2 hi;
            conv4h(va[q], hi);
            const int b0 = arow * PIT + af4 * 2 + q * 8;
            *(uint2*)(pH + b0) = hi;
        }
    };

    auto CPB = [&](int c, int buf) {
        constexpr int ITER = CH / 256;   // 5 or 2
#pragma unroll
        for (int i = 0; i < ITER; ++i) {
            const int it = tid + i * 256;
            const int r  = it >> 2, c4 = it & 3;
            const __half* src = Wh + (size_t)r * WSTR + c * 32 + c4 * 8;
            const uint32_t dst = sb + OFF_B + buf * BBUF + (r * PIT + c4 * 4) * 4;
            cpa16(dst, src);
        }
        CP_COMMIT();
    };

    // ldmatrix lane addresses (pitch 20 words = 80 B, conflict-free)
    const uint32_t aBase = sb + ((uint32_t)(wm * 32 + (lane & 15)) * PIT + ((lane >> 4) << 2)) * 4;
    const uint32_t bBase = sb + OFF_B +
        ((uint32_t)(wn * WN + ((lane >> 4) << 3) + (lane & 7)) * PIT + (((lane >> 3) & 1) << 2)) * 4;
    constexpr uint32_t AROW16 = 16 * PIT * 4;    // 1280
    constexpr uint32_t BROW16 = 16 * PIT * 4;    // 1280 per j-pair

    // prologue
    LDA(0);
    CPB(0, 0);
    STSA(0);
    CP_WAIT0();
    __syncthreads();

    const int fr = lane >> 2;   // 0..7
    const int fq = lane & 3;    // 0..3

    for (int c = 0; c < KSTG; ++c) {
        const int cur = c & 1;
        if (c + 1 < KSTG) { LDA(c + 1); CPB(c + 1, cur ^ 1); }

        const uint32_t aOff = (uint32_t)cur * ABUF;
        const uint32_t bOff = (uint32_t)cur * BBUF;

#pragma unroll
        for (int kk = 0; kk < 2; ++kk) {
            const uint32_t kb = kk * 32;   // 16 fp16 = 32 bytes per kk
            uint32_t ah0[4], ah1[4];
            ldsm4(aBase + aOff + kb,          ah0[0], ah0[1], ah0[2], ah0[3]);
            ldsm4(aBase + aOff + AROW16 + kb, ah1[0], ah1[1], ah1[2], ah1[3]);
#pragma unroll
            for (int jp = 0; jp < JP; ++jp) {
                uint32_t b4[4];   // two n-frags, JIT load (4 live regs)
                ldsm4(bBase + bOff + (uint32_t)jp * BROW16 + kb,
                      b4[0], b4[1], b4[2], b4[3]);
                mma16h(acc[0][2 * jp],     ah0, b4);
                mma16h(acc[1][2 * jp],     ah1, b4);
                mma16h(acc[0][2 * jp + 1], ah0, b4 + 2);
                mma16h(acc[1][2 * jp + 1], ah1, b4 + 2);
            }
        }

        if (c + 1 < KSTG) { STSA(cur ^ 1); CP_WAIT0(); }
        __syncthreads();
    }

    // ---- epilogue: bias + relu + fp16 store + fused column stats ----
    const int r0 = mblk + wm * 32 + fr;
#pragma unroll
    for (int j = 0; j < J; ++j) {
        const int colg = wn * WN + j * 8 + fq * 2;
        const bool cv = colg < NVG;
        const float b0v = cv ? __ldg(bias + colg)     : 0.f;
        const float b1v = cv ? __ldg(bias + colg + 1) : 0.f;
        float s0 = 0.f, s1 = 0.f, q0 = 0.f, q1 = 0.f;
#pragma unroll
        for (int i = 0; i < 2; ++i) {
            float v0 = fmaxf(acc[i][j][0] + b0v, 0.f);
            float v1 = fmaxf(acc[i][j][1] + b1v, 0.f);
            float v2 = fmaxf(acc[i][j][2] + b0v, 0.f);
            float v3 = fmaxf(acc[i][j][3] + b1v, 0.f);
            if (cv) {
                *(__half2*)(OUT + (size_t)(r0 + i * 16) * OSTR + colg) =
                    __floats2half2_rn(v0, v1);
                *(__half2*)(OUT + (size_t)(r0 + i * 16 + 8) * OSTR + colg) =
                    __floats2half2_rn(v2, v3);
            }
            s0 += v0 + v2; s1 += v1 + v3;
            q0 += v0 * v0 + v2 * v2; q1 += v1 * v1 + v3 * v3;
        }
#pragma unroll
        for (int off = 4; off < 32; off <<= 1) {
            s0 += __shfl_xor_sync(0xffffffffu, s0, off);
            s1 += __shfl_xor_sync(0xffffffffu, s1, off);
            q0 += __shfl_xor_sync(0xffffffffu, q0, off);
            q1 += __shfl_xor_sync(0xffffffffu, q1, off);
        }
        if (lane < 4 && cv) {
            atomicAdd(sumP + colg, s0);
            atomicAdd(sumP + colg + 1, s1);
            atomicAdd(sqP + colg, q0);
            atomicAdd(sqP + colg + 1, q1);
        }
    }
}

// ---------------- bf16 3-term kernel for layer 3 (tiny GEMM, h2 fp16 input) ----------
// BN2 coefficients computed per-CTA from g_sum2/g_sq2 — no finalize kernel.
__device__ __forceinline__ void split4(float4 v, uint32_t& h0, uint32_t& h1,
                                       uint32_t& l0, uint32_t& l1) {
    uint2 hi, lo;
    split4v(v, hi, lo);
    h0 = hi.x; h1 = hi.y; l0 = lo.x; l1 = lo.y;
}

__global__ void __launch_bounds__(256, 2)
gemm3_legacy(const float* __restrict__ W, const float* __restrict__ bias,
             const float* __restrict__ S, const float* __restrict__ Mn,
             const float* __restrict__ G, const float* __restrict__ BE,
             float* __restrict__ OUTF)
{
    constexpr int K = 100, KS = 7, NV = 10, ASTR = 128, NSTR = 100, OSTR = 10;

    __shared__ __align__(16) uint32_t sAh[128 * 12];
    __shared__ __align__(16) uint32_t sAl[128 * 12];
    __shared__ __align__(16) uint32_t sBh[64 * 12];
    __shared__ __align__(16) uint32_t sBl[64 * 12];
    __shared__ __align__(16) float sScale[112];
    __shared__ __align__(16) float sShift[112];

    const int tid  = threadIdx.x;
    const int lane = tid & 31;
    const int wid  = tid >> 5;
    const int wm   = wid >> 1;
    const int wn   = wid & 1;
    const int mblk = blockIdx.x * 128;
    const int la_m = tid >> 2;
    const int la_c = (tid & 3) << 2;

    for (int i = tid; i < K; i += 256) {
        float sc, sh;
        bn_coeff(g_sum2[i], g_sq2[i], G[i], BE[i], sc, sh);
        sScale[i] = sc;
        sShift[i] = sh;
    }
    __syncthreads();

    float acc[2][4][4];
#pragma unroll
    for (int i = 0; i < 2; i++)
#pragma unroll
        for (int j = 0; j < 4; j++)
#pragma unroll
            for (int c = 0; c < 4; c++) acc[i][j][c] = 0.f;

    float4 va0, va1, vb;
    auto LOADA = [&](int s, float4& o0, float4& o1) {
        const int k0 = s * 16 + la_c;
        if (k0 + 3 < K) {
            const int m0 = mblk + la_m;
            float4 h0 = h4_to_f4(*(const uint2*)(g_h2 + (size_t)m0 * ASTR + k0));
            float4 h1 = h4_to_f4(*(const uint2*)(g_h2 + (size_t)(m0 + 64) * ASTR + k0));
            float4 s0 = *(const float4*)(S + (size_t)m0 * NSTR + k0);
            float4 s1 = *(const float4*)(S + (size_t)(m0 + 64) * NSTR + k0);
            float4 q0 = *(const float4*)(Mn + (size_t)m0 * NSTR + k0);
            float4 q1 = *(const float4*)(Mn + (size_t)(m0 + 64) * NSTR + k0);
            float4 sc = *(const float4*)(sScale + k0);
            float4 sh = *(const float4*)(sShift + k0);
            o0.x = fmaf(s0.x, fmaf(sc.x, h0.x, sh.x), q0.x);
            o0.y = fmaf(s0.y, fmaf(sc.y, h0.y, sh.y), q0.y);
            o0.z = fmaf(s0.z, fmaf(sc.z, h0.z, sh.z), q0.z);
            o0.w = fmaf(s0.w, fmaf(sc.w, h0.w, sh.w), q0.w);
            o1.x = fmaf(s1.x, fmaf(sc.x, h1.x, sh.x), q1.x);
            o1.y = fmaf(s1.y, fmaf(sc.y, h1.y, sh.y), q1.y);
            o1.z = fmaf(s1.z, fmaf(sc.z, h1.z, sh.z), q1.z);
            o1.w = fmaf(s1.w, fmaf(sc.w, h1.w, sh.w), q1.w);
        } else {
            o0 = make_float4(0.f, 0.f, 0.f, 0.f);
            o1 = make_float4(0.f, 0.f, 0.f, 0.f);
        }
    };
    auto LOADB = [&](int s, float4& o) {
        const int k0 = s * 16 + la_c;
        const int n  = la_m;
        const bool ok = (n < NV) && (k0 + 3 < K);
        o = ok ? *(const float4*)(W + (size_t)n * K + k0)
               : make_float4(0.f, 0.f, 0.f, 0.f);
    };

    LOADA(0, va0, va1);
    LOADB(0, vb);

    const int r4 = lane >> 2;
    const int tg = lane & 3;

    for (int s = 0; s < KS; ++s) {
        {
            const int wbase = la_m * 12 + (la_c >> 1);
            uint32_t h0, h1, l0, l1;
            split4(va0, h0, h1, l0, l1);
            sAh[wbase] = h0; sAh[wbase + 1] = h1;
            sAl[wbase] = l0; sAl[wbase + 1] = l1;
            split4(va1, h0, h1, l0, l1);
            sAh[wbase + 768] = h0; sAh[wbase + 769] = h1;
            sAl[wbase + 768] = l0; sAl[wbase + 769] = l1;
            split4(vb, h0, h1, l0, l1);
            sBh[wbase] = h0; sBh[wbase + 1] = h1;
            sBl[wbase] = l0; sBl[wbase + 1] = l1;
        }
        __syncthreads();
        if (s + 1 < KS) { LOADA(s + 1, va0, va1); LOADB(s + 1, vb); }

        uint32_t ah[2][4], al[2][4], bh[4][2], bl[4][2];
#pragma unroll
        for (int i = 0; i < 2; i++) {
            const int base = (wm * 32 + i * 16 + r4) * 12 + tg;
            ah[i][0] = sAh[base];       ah[i][1] = sAh[base + 96];
            ah[i][2] = sAh[base + 4];   ah[i][3] = sAh[base + 100];
            al[i][0] = sAl[base];       al[i][1] = sAl[base + 96];
            al[i][2] = sAl[base + 4];   al[i][3] = sAl[base + 100];
        }
#pragma unroll
        for (int j = 0; j < 4; j++) {
            const int base = (wn * 32 + j * 8 + r4) * 12 + tg;
            bh[j][0] = sBh[base]; bh[j][1] = sBh[base + 4];
            bl[j][0] = sBl[base]; bl[j][1] = sBl[base + 4];
        }
#pragma unroll
        for (int i = 0; i < 2; i++)
#pragma unroll
            for (int j = 0; j < 4; j++) {
                mma16(acc[i][j], ah[i], bh[j]);
                mma16(acc[i][j], ah[i], bl[j]);
                mma16(acc[i][j], al[i], bh[j]);
            }
        __syncthreads();
    }

#pragma unroll
    for (int i = 0; i < 2; i++)
#pragma unroll
        for (int j = 0; j < 4; j++)
#pragma unroll
            for (int c = 0; c < 4; c++) {
                const int row = mblk + wm * 32 + i * 16 + r4 + ((c & 2) ? 8 : 0);
                const int col = wn * 32 + j * 8 + 2 * tg + (c & 1);
                if (col < NV) {
                    float v = acc[i][j][c] + __ldg(bias + col);
                    OUTF[(size_t)row * OSTR + col] = v;
                }
            }
}

// ---------------- launch ----------------
extern "C" void kernel_launch(void* const* d_in, const int* in_sizes, int n_in,
                              void* d_out, int out_size) {
    const float* x   = (const float*)d_in[0];
    const float* W1  = (const float*)d_in[1];
    const float* b1  = (const float*)d_in[2];
    const float* g1  = (const float*)d_in[3];
    const float* be1 = (const float*)d_in[4];
    const float* s1  = (const float*)d_in[5];
    const float* m1  = (const float*)d_in[6];
    const float* W2  = (const float*)d_in[7];
    const float* b2  = (const float*)d_in[8];
    const float* g2  = (const float*)d_in[9];
    const float* be2 = (const float*)d_in[10];
    const float* s2  = (const float*)d_in[11];
    const float* m2  = (const float*)d_in[12];
    const float* W3  = (const float*)d_in[13];
    const float* b3  = (const float*)d_in[14];
    float* out = (float*)d_out;

    const int SM1 = 2 * 5120 + 2 * (320 * 20 * 4);              // 61440
    const int SM2 = 2 * 5120 + 2 * (128 * 20 * 4) + 2560;       // 33280
    cudaFuncSetAttribute(tc_gemm<1>, cudaFuncAttributeMaxDynamicSharedMemorySize, SM1);
    cudaFuncSetAttribute(tc_gemm<2>, cudaFuncAttributeMaxDynamicSharedMemorySize, SM2);

    split_w<<<1200, 256>>>(W1, W2);
    tc_gemm<1><<<1024, 256, SM1>>>(x, b1, nullptr, nullptr, nullptr, nullptr);
    tc_gemm<2><<<1024, 256, SM2>>>(nullptr, b2, s1, m1, g1, be1);
    gemm3_legacy<<<512, 256>>>(W3, b3, s2, m2, g2, be2, out);
}